// round 6
// baseline (speedup 1.0000x reference)
#include <cuda_runtime.h>
#include <cuda_bf16.h>
#include <stdint.h>

#define NB   4
#define CIN  256
#define COUT 256
#define HH   96
#define WW   96
#define HWSZ (HH*WW)          // 9216
#define KK2  9
#define CK   (CIN*KK2)        // 2304
#define NOFF 18
#define NCHUNK 36             // CK / 64
#define KC   64
#define ZSPLIT 8
#define PX   64               // pixels per CTA

// ---- dynamic smem layout for dcn_hmma (u32 / bytes) ----
// B buffer: 32 kpairs x 72 u32 (stride-72 = conflict-free), hi then lo.
#define BSTRIDE   72
#define BHALF_U32 (32*BSTRIDE)          // 2304 u32 = 9216 B
#define BBUF_BYTES (2*BHALF_U32*4)      // 18432 B (hi+lo)
#define OFF_IDX    (2*BBUF_BYTES)       // 36864
#define OFF_SWT    (OFF_IDX + KK2*PX*16)// 46080
#define SMEM_BYTES (OFF_SWT + KK2*PX*16)// 55296

// ---- device scratch (allocation-free rule) ----
__device__ float    g_off_part[ZSPLIT*NB*NOFF*HWSZ];   // 21 MB
__device__ float    g_offset[NB*NOFF*HWSZ];            // 2.65 MB
__device__ uint32_t g_wfrag[NCHUNK*2*16*32*16];        // 2.36 MB: A fragments, hi/lo

// ---------------------------------------------------------------------------
// Kernel A1: partial offset conv (32 Cin channels per block.z chunk)
// ---------------------------------------------------------------------------
__global__ __launch_bounds__(128) void offset_part(
    const float* __restrict__ x, const float* __restrict__ w_off)
{
    __shared__ float ws[8*NOFF*KK2];
    int b   = blockIdx.y, z = blockIdx.z;
    int tid = threadIdx.x;
    int p0  = blockIdx.x * 256 + tid;
    int p1  = p0 + 128;
    int yy0 = p0 / WW, xx0 = p0 % WW;
    int yy1 = p1 / WW, xx1 = p1 % WW;

    float acc[2][NOFF];
    #pragma unroll
    for (int j = 0; j < NOFF; j++) { acc[0][j] = 0.f; acc[1][j] = 0.f; }

    const float* xb = x + (size_t)b * CIN * HWSZ;
    const int CPZ = CIN / ZSPLIT;   // 32

    for (int c0 = z*CPZ; c0 < z*CPZ + CPZ; c0 += 8) {
        __syncthreads();
        for (int l = tid; l < 8*NOFF*KK2; l += 128) {
            int ci = l / (NOFF*KK2);
            int r  = l % (NOFF*KK2);
            int j  = r / KK2, k = r % KK2;
            ws[l] = w_off[((size_t)(j*CIN + c0 + ci))*KK2 + k];
        }
        __syncthreads();
        #pragma unroll 2
        for (int ci = 0; ci < 8; ci++) {
            const float* xp = xb + (size_t)(c0 + ci) * HWSZ;
            float xv0[9], xv1[9];
            #pragma unroll
            for (int ky = 0; ky < 3; ky++) {
                #pragma unroll
                for (int kx = 0; kx < 3; kx++) {
                    int iy = yy0 - 1 + ky, ix = xx0 - 1 + kx;
                    xv0[ky*3+kx] = (iy >= 0 && iy < HH && ix >= 0 && ix < WW) ? xp[iy*WW + ix] : 0.f;
                    iy = yy1 - 1 + ky; ix = xx1 - 1 + kx;
                    xv1[ky*3+kx] = (iy >= 0 && iy < HH && ix >= 0 && ix < WW) ? xp[iy*WW + ix] : 0.f;
                }
            }
            const float* wsc = ws + ci * NOFF * KK2;
            #pragma unroll
            for (int j = 0; j < NOFF; j++) {
                #pragma unroll
                for (int k = 0; k < KK2; k++) {
                    float wv = wsc[j*KK2 + k];
                    acc[0][j] += xv0[k] * wv;
                    acc[1][j] += xv1[k] * wv;
                }
            }
        }
    }
    size_t zb = (size_t)z * NB * NOFF * HWSZ;
    #pragma unroll
    for (int j = 0; j < NOFF; j++) {
        g_off_part[zb + ((size_t)b*NOFF + j)*HWSZ + p0] = acc[0][j];
        g_off_part[zb + ((size_t)b*NOFF + j)*HWSZ + p1] = acc[1][j];
    }
}

// Kernel A2: sum partials + bias
__global__ void offset_reduce(const float* __restrict__ b_off)
{
    int i = blockIdx.x * 256 + threadIdx.x;
    if (i < NB*NOFF*HWSZ) {
        int j = (i / HWSZ) % NOFF;
        float s = b_off[j];
        #pragma unroll
        for (int z = 0; z < ZSPLIT; z++) s += g_off_part[(size_t)z*NB*NOFF*HWSZ + i];
        g_offset[i] = s;
    }
}

// ---------------------------------------------------------------------------
// Kernel B: pack w_def into bf16 hi/lo A-fragments (m16n8k16 layout).
// u32 index bits (lane fastest below i): [i:2][lane:5][ks:2][mb:4][h:1][chunk]
// ---------------------------------------------------------------------------
__global__ void wprep(const float* __restrict__ w_def)
{
    int idx = blockIdx.x * 256 + threadIdx.x;
    if (idx >= NCHUNK*2*16*32*16) return;
    int i     =  idx        & 3;
    int lane  = (idx >> 2)  & 31;
    int ks    = (idx >> 7)  & 3;
    int mb    = (idx >> 9)  & 15;
    int h     = (idx >> 13) & 1;
    int chunk =  idx >> 14;

    int o = mb*16 + (lane >> 2) + (i & 1)*8;
    int k = chunk*64 + ks*16 + (lane & 3)*2 + (i >> 1)*8;
    float w0 = w_def[(size_t)o*CK + k];
    float w1 = w_def[(size_t)o*CK + k + 1];

    __nv_bfloat16 v0, v1;
    if (h == 0) {
        v0 = __float2bfloat16(w0);
        v1 = __float2bfloat16(w1);
    } else {
        v0 = __float2bfloat16(w0 - __bfloat162float(__float2bfloat16(w0)));
        v1 = __float2bfloat16(w1 - __bfloat162float(__float2bfloat16(w1)));
    }
    g_wfrag[idx] = (uint32_t)__bfloat16_as_ushort(v0)
                 | ((uint32_t)__bfloat16_as_ushort(v1) << 16);
}

// ---------------------------------------------------------------------------
__device__ __forceinline__ void mma16816(float* c, uint4 a, uint32_t b0, uint32_t b1)
{
    asm volatile(
        "mma.sync.aligned.m16n8k16.row.col.f32.bf16.bf16.f32 "
        "{%0,%1,%2,%3}, {%4,%5,%6,%7}, {%8,%9}, {%0,%1,%2,%3};"
        : "+f"(c[0]), "+f"(c[1]), "+f"(c[2]), "+f"(c[3])
        : "r"(a.x), "r"(a.y), "r"(a.z), "r"(a.w), "r"(b0), "r"(b1));
}

// ---------------------------------------------------------------------------
// Kernel C: fused bilinear-gather + 3-pass bf16 HMMA GEMM,
// producer/consumer warp specialized.
// CTA: 64 px x 256 Cout; 512 threads = 16 warps.
//   warps 0-7  : consumers (4 m-rows x 2 n-cols, warp tile 64x32)
//   warps 8-15 : producers (gather + bf16 split + STS)
// grid = NB*HWSZ/64 = 576. 1 CTA/SM (RF-limited).
// ---------------------------------------------------------------------------
__global__ void __launch_bounds__(512, 1) dcn_hmma(
    const float* __restrict__ x,
    float* __restrict__ out,
    const float* __restrict__ b_def)
{
    extern __shared__ __align__(16) unsigned char smem_raw[];
    int4*   s_idx = (int4*)  (smem_raw + OFF_IDX);
    float4* s_wt  = (float4*)(smem_raw + OFF_SWT);

    int tid = threadIdx.x, wid = tid >> 5, lane = tid & 31;

    int gp    = blockIdx.x * PX;
    int b     = gp / HWSZ;
    int pbase = gp % HWSZ;

    // Phase 1 (all threads): bilinear corner indices & weights, 64-px tile
    for (int l = tid; l < KK2*PX; l += 512) {
        int k2 = l >> 6, pl = l & 63;
        int p  = pbase + pl;
        int oy = p / WW, ox = p % WW;
        float offy = g_offset[((size_t)b*NOFF + k2*2    )*HWSZ + p];
        float offx = g_offset[((size_t)b*NOFF + k2*2 + 1)*HWSZ + p];
        int ky = k2 / 3, kx = k2 % 3;
        float py = (float)(oy - 1 + ky) + offy;
        float px = (float)(ox - 1 + kx) + offx;
        float y0f = floorf(py), x0f = floorf(px);
        float wy1 = py - y0f, wy0 = 1.f - wy1;
        float wx1 = px - x0f, wx0 = 1.f - wx1;
        int iy0 = (int)y0f, ix0 = (int)x0f;
        int iy1 = iy0 + 1,  ix1 = ix0 + 1;
        bool vy0 = (iy0 >= 0) && (iy0 < HH), vy1 = (iy1 >= 0) && (iy1 < HH);
        bool vx0 = (ix0 >= 0) && (ix0 < WW), vx1 = (ix1 >= 0) && (ix1 < WW);
        int cy0 = min(max(iy0, 0), HH-1), cy1 = min(max(iy1, 0), HH-1);
        int cx0 = min(max(ix0, 0), WW-1), cx1 = min(max(ix1, 0), WW-1);
        s_idx[l] = make_int4(cy0*WW + cx0, cy0*WW + cx1, cy1*WW + cx0, cy1*WW + cx1);
        s_wt[l]  = make_float4((vy0 && vx0) ? wy0*wx0 : 0.f,
                               (vy0 && vx1) ? wy0*wx1 : 0.f,
                               (vy1 && vx0) ? wy1*wx0 : 0.f,
                               (vy1 && vx1) ? wy1*wx1 : 0.f);
    }
    __syncthreads();

    const float* xb = x + (size_t)b * CIN * HWSZ;

    if (wid >= 8) {
        // ================= PRODUCER warps (8-15) =================
        int ptid = tid - 256;   // 0..255
        #pragma unroll 1
        for (int chunk = 0; chunk < NCHUNK + 1; ++chunk) {
            if (chunk < NCHUNK) {
                uint32_t* sBhi = (uint32_t*)(smem_raw + (chunk & 1) * BBUF_BYTES);
                uint32_t* sBlo = sBhi + BHALF_U32;
                int ck0 = chunk * KC;
                #pragma unroll
                for (int it = 0; it < 8; it++) {
                    int l  = it*256 + ptid;
                    int kp = l >> 6, pl = l & 63;
                    int ck = ck0 + kp*2;
                    int c  = ck / 9, k2 = ck - c*9;
                    int4   id = s_idx[k2*PX + pl];
                    float4 w  = s_wt [k2*PX + pl];
                    const float* xp = xb + (size_t)c * HWSZ;
                    float v0 = w.x*__ldg(xp+id.x) + w.y*__ldg(xp+id.y)
                             + w.z*__ldg(xp+id.z) + w.w*__ldg(xp+id.w);
                    int ck1 = ck + 1;
                    int c1  = ck1 / 9, k21 = ck1 - c1*9;
                    id = s_idx[k21*PX + pl];
                    w  = s_wt [k21*PX + pl];
                    xp = xb + (size_t)c1 * HWSZ;
                    float v1 = w.x*__ldg(xp+id.x) + w.y*__ldg(xp+id.y)
                             + w.z*__ldg(xp+id.z) + w.w*__ldg(xp+id.w);

                    __nv_bfloat16 h0 = __float2bfloat16(v0);
                    __nv_bfloat16 h1 = __float2bfloat16(v1);
                    __nv_bfloat16 l0 = __float2bfloat16(v0 - __bfloat162float(h0));
                    __nv_bfloat16 l1 = __float2bfloat16(v1 - __bfloat162float(h1));
                    sBhi[kp*BSTRIDE + pl] = (uint32_t)__bfloat16_as_ushort(h0)
                                          | ((uint32_t)__bfloat16_as_ushort(h1) << 16);
                    sBlo[kp*BSTRIDE + pl] = (uint32_t)__bfloat16_as_ushort(l0)
                                          | ((uint32_t)__bfloat16_as_ushort(l1) << 16);
                }
            }
            __syncthreads();   // chunk ready / previous buffer free
        }
    } else {
        // ================= CONSUMER warps (0-7) =================
        int mrow = wid >> 1, ncol = wid & 1;
        const uint4* wfrag4 = (const uint4*)g_wfrag;

        float acc[4][4][4];
        #pragma unroll
        for (int i = 0; i < 4; i++)
            #pragma unroll
            for (int j = 0; j < 4; j++)
                #pragma unroll
                for (int e = 0; e < 4; e++) acc[i][j][e] = 0.f;

        __syncthreads();   // wait for producers: chunk 0 ready
        #pragma unroll 1
        for (int chunk = 0; chunk < NCHUNK; ++chunk) {
            uint32_t* sBhi = (uint32_t*)(smem_raw + (chunk & 1) * BBUF_BYTES);
            uint32_t* sBlo = sBhi + BHALF_U32;

            #pragma unroll
            for (int ks = 0; ks < 4; ks++) {
                uint32_t bh0[4], bh1[4], bl0[4], bl1[4];
                #pragma unroll
                for (int nb = 0; nb < 4; nb++) {
                    int col = ncol*32 + nb*8 + (lane >> 2);
                    int kpb = ks*8 + (lane & 3);
                    bh0[nb] = sBhi[ kpb     *BSTRIDE + col];
                    bh1[nb] = sBhi[(kpb + 4)*BSTRIDE + col];
                    bl0[nb] = sBlo[ kpb     *BSTRIDE + col];
                    bl1[nb] = sBlo[(kpb + 4)*BSTRIDE + col];
                }
                #pragma unroll
                for (int mb = 0; mb < 4; mb++) {
                    int mbg = mrow*4 + mb;
                    uint4 ahi = __ldg(wfrag4 + ((size_t)((chunk*2    )*16 + mbg)*4 + ks)*32 + lane);
                    uint4 alo = __ldg(wfrag4 + ((size_t)((chunk*2 + 1)*16 + mbg)*4 + ks)*32 + lane);
                    #pragma unroll
                    for (int nb = 0; nb < 4; nb++) {
                        mma16816(acc[mb][nb], ahi, bh0[nb], bh1[nb]);
                        mma16816(acc[mb][nb], ahi, bl0[nb], bl1[nb]);
                        mma16816(acc[mb][nb], alo, bh0[nb], bh1[nb]);
                    }
                }
            }
            __syncthreads();   // done with this buffer; next chunk ready
        }

        // ---- epilogue: bias + store (float2 per fragment pair) ----
        #pragma unroll
        for (int mb = 0; mb < 4; mb++) {
            int o0 = mrow*64 + mb*16 + (lane >> 2);
            float bd0 = b_def[o0], bd8 = b_def[o0 + 8];
            float* r0 = out + ((size_t)b*COUT + o0)*HWSZ + pbase + ncol*32 + (lane & 3)*2;
            float* r8 = r0 + (size_t)8*HWSZ;
            #pragma unroll
            for (int nb = 0; nb < 4; nb++) {
                float2 v0 = make_float2(acc[mb][nb][0] + bd0, acc[mb][nb][1] + bd0);
                float2 v8 = make_float2(acc[mb][nb][2] + bd8, acc[mb][nb][3] + bd8);
                *(float2*)(r0 + nb*8) = v0;
                *(float2*)(r8 + nb*8) = v8;
            }
        }
    }
}

// ---------------------------------------------------------------------------
extern "C" void kernel_launch(void* const* d_in, const int* in_sizes, int n_in,
                              void* d_out, int out_size)
{
    const float* x     = (const float*)d_in[0];
    const float* w_off = (const float*)d_in[1];
    const float* b_off = (const float*)d_in[2];
    const float* w_def = (const float*)d_in[3];
    const float* b_def = (const float*)d_in[4];
    float* out = (float*)d_out;

    cudaFuncSetAttribute(dcn_hmma, cudaFuncAttributeMaxDynamicSharedMemorySize, SMEM_BYTES);

    offset_part<<<dim3(HWSZ/256, NB, ZSPLIT), 128>>>(x, w_off);
    offset_reduce<<<(NB*NOFF*HWSZ + 255)/256, 256>>>(b_off);
    wprep<<<(NCHUNK*2*16*32*16 + 255)/256, 256>>>(w_def);
    dcn_hmma<<<NB*HWSZ/PX, 512, SMEM_BYTES>>>(x, out, b_def);
}

// round 7
// speedup vs baseline: 1.0185x; 1.0185x over previous
#include <cuda_runtime.h>
#include <cuda_bf16.h>
#include <stdint.h>

#define NB   4
#define CIN  256
#define COUT 256
#define HH   96
#define WW   96
#define HWSZ (HH*WW)          // 9216
#define KK2  9
#define CK   (CIN*KK2)        // 2304
#define NOFF 18
#define NCHUNK 36             // CK / 64
#define KC   64
#define ZSPLIT 8
#define PX   64               // pixels per CTA

// ---- dynamic smem layout for dcn_hmma (u32 / bytes) ----
// B buffer: 32 kpairs x 72 u32 (stride-72 = conflict-free), hi then lo.
#define BSTRIDE   72
#define BHALF_U32 (32*BSTRIDE)          // 2304 u32 = 9216 B
#define BBUF_BYTES (2*BHALF_U32*4)      // 18432 B (hi+lo)
#define OFF_IDX    (2*BBUF_BYTES)       // 36864
#define OFF_SWT    (OFF_IDX + KK2*PX*16)// 46080
#define SMEM_BYTES (OFF_SWT + KK2*PX*16)// 55296

// ---- device scratch (allocation-free rule) ----
__device__ float    g_off_part[ZSPLIT*NB*NOFF*HWSZ];   // 21 MB
__device__ float    g_offset[NB*NOFF*HWSZ];            // 2.65 MB
__device__ uint32_t g_wfrag[NCHUNK*2*16*32*16];        // 2.36 MB: A fragments, hi/lo

// ---------------------------------------------------------------------------
// Kernel A1: partial offset conv (32 Cin channels per block.z chunk)
// ---------------------------------------------------------------------------
__global__ __launch_bounds__(128) void offset_part(
    const float* __restrict__ x, const float* __restrict__ w_off)
{
    __shared__ float ws[8*NOFF*KK2];
    int b   = blockIdx.y, z = blockIdx.z;
    int tid = threadIdx.x;
    int p0  = blockIdx.x * 256 + tid;
    int p1  = p0 + 128;
    int yy0 = p0 / WW, xx0 = p0 % WW;
    int yy1 = p1 / WW, xx1 = p1 % WW;

    float acc[2][NOFF];
    #pragma unroll
    for (int j = 0; j < NOFF; j++) { acc[0][j] = 0.f; acc[1][j] = 0.f; }

    const float* xb = x + (size_t)b * CIN * HWSZ;
    const int CPZ = CIN / ZSPLIT;   // 32

    for (int c0 = z*CPZ; c0 < z*CPZ + CPZ; c0 += 8) {
        __syncthreads();
        for (int l = tid; l < 8*NOFF*KK2; l += 128) {
            int ci = l / (NOFF*KK2);
            int r  = l % (NOFF*KK2);
            int j  = r / KK2, k = r % KK2;
            ws[l] = w_off[((size_t)(j*CIN + c0 + ci))*KK2 + k];
        }
        __syncthreads();
        #pragma unroll 2
        for (int ci = 0; ci < 8; ci++) {
            const float* xp = xb + (size_t)(c0 + ci) * HWSZ;
            float xv0[9], xv1[9];
            #pragma unroll
            for (int ky = 0; ky < 3; ky++) {
                #pragma unroll
                for (int kx = 0; kx < 3; kx++) {
                    int iy = yy0 - 1 + ky, ix = xx0 - 1 + kx;
                    xv0[ky*3+kx] = (iy >= 0 && iy < HH && ix >= 0 && ix < WW) ? xp[iy*WW + ix] : 0.f;
                    iy = yy1 - 1 + ky; ix = xx1 - 1 + kx;
                    xv1[ky*3+kx] = (iy >= 0 && iy < HH && ix >= 0 && ix < WW) ? xp[iy*WW + ix] : 0.f;
                }
            }
            const float* wsc = ws + ci * NOFF * KK2;
            #pragma unroll
            for (int j = 0; j < NOFF; j++) {
                #pragma unroll
                for (int k = 0; k < KK2; k++) {
                    float wv = wsc[j*KK2 + k];
                    acc[0][j] += xv0[k] * wv;
                    acc[1][j] += xv1[k] * wv;
                }
            }
        }
    }
    size_t zb = (size_t)z * NB * NOFF * HWSZ;
    #pragma unroll
    for (int j = 0; j < NOFF; j++) {
        g_off_part[zb + ((size_t)b*NOFF + j)*HWSZ + p0] = acc[0][j];
        g_off_part[zb + ((size_t)b*NOFF + j)*HWSZ + p1] = acc[1][j];
    }
}

// Kernel A2: sum partials + bias
__global__ void offset_reduce(const float* __restrict__ b_off)
{
    int i = blockIdx.x * 256 + threadIdx.x;
    if (i < NB*NOFF*HWSZ) {
        int j = (i / HWSZ) % NOFF;
        float s = b_off[j];
        #pragma unroll
        for (int z = 0; z < ZSPLIT; z++) s += g_off_part[(size_t)z*NB*NOFF*HWSZ + i];
        g_offset[i] = s;
    }
}

// ---------------------------------------------------------------------------
// Kernel B: pack w_def into bf16 hi/lo A-fragments (m16n8k16 layout).
// u32 index bits (lane fastest below i): [i:2][lane:5][ks:2][mb:4][h:1][chunk]
// ---------------------------------------------------------------------------
__global__ void wprep(const float* __restrict__ w_def)
{
    int idx = blockIdx.x * 256 + threadIdx.x;
    if (idx >= NCHUNK*2*16*32*16) return;
    int i     =  idx        & 3;
    int lane  = (idx >> 2)  & 31;
    int ks    = (idx >> 7)  & 3;
    int mb    = (idx >> 9)  & 15;
    int h     = (idx >> 13) & 1;
    int chunk =  idx >> 14;

    int o = mb*16 + (lane >> 2) + (i & 1)*8;
    int k = chunk*64 + ks*16 + (lane & 3)*2 + (i >> 1)*8;
    float w0 = w_def[(size_t)o*CK + k];
    float w1 = w_def[(size_t)o*CK + k + 1];

    __nv_bfloat16 v0, v1;
    if (h == 0) {
        v0 = __float2bfloat16(w0);
        v1 = __float2bfloat16(w1);
    } else {
        v0 = __float2bfloat16(w0 - __bfloat162float(__float2bfloat16(w0)));
        v1 = __float2bfloat16(w1 - __bfloat162float(__float2bfloat16(w1)));
    }
    g_wfrag[idx] = (uint32_t)__bfloat16_as_ushort(v0)
                 | ((uint32_t)__bfloat16_as_ushort(v1) << 16);
}

// ---------------------------------------------------------------------------
__device__ __forceinline__ void mma16816(float* c, uint4 a, uint32_t b0, uint32_t b1)
{
    asm volatile(
        "mma.sync.aligned.m16n8k16.row.col.f32.bf16.bf16.f32 "
        "{%0,%1,%2,%3}, {%4,%5,%6,%7}, {%8,%9}, {%0,%1,%2,%3};"
        : "+f"(c[0]), "+f"(c[1]), "+f"(c[2]), "+f"(c[3])
        : "r"(a.x), "r"(a.y), "r"(a.z), "r"(a.w), "r"(b0), "r"(b1));
}

// ---------------------------------------------------------------------------
// Kernel C: fused bilinear-gather + 3-pass bf16 HMMA GEMM.
// Intra-warp pipelining: per ks-step, issue chunk(i+1) batch LDGs, run MMA(i),
// then combine+store the prefetched values. CTA: 64 px x 256 Cout; 256 thr
// = 8 warps (4 m-rows x 2 n-cols, warp tile 64x32). grid 576, 2 CTAs/SM.
// ---------------------------------------------------------------------------
__global__ void __launch_bounds__(256, 2) dcn_hmma(
    const float* __restrict__ x,
    float* __restrict__ out,
    const float* __restrict__ b_def)
{
    extern __shared__ __align__(16) unsigned char smem_raw[];
    int4*   s_idx = (int4*)  (smem_raw + OFF_IDX);
    float4* s_wt  = (float4*)(smem_raw + OFF_SWT);

    int tid = threadIdx.x, wid = tid >> 5, lane = tid & 31;
    int mrow = wid >> 1, ncol = wid & 1;

    int gp    = blockIdx.x * PX;
    int b     = gp / HWSZ;
    int pbase = gp % HWSZ;

    // Phase 1: bilinear corner indices & weights for this 64-pixel tile
    for (int l = tid; l < KK2*PX; l += 256) {
        int k2 = l >> 6, pl = l & 63;
        int p  = pbase + pl;
        int oy = p / WW, ox = p % WW;
        float offy = g_offset[((size_t)b*NOFF + k2*2    )*HWSZ + p];
        float offx = g_offset[((size_t)b*NOFF + k2*2 + 1)*HWSZ + p];
        int ky = k2 / 3, kx = k2 % 3;
        float py = (float)(oy - 1 + ky) + offy;
        float px = (float)(ox - 1 + kx) + offx;
        float y0f = floorf(py), x0f = floorf(px);
        float wy1 = py - y0f, wy0 = 1.f - wy1;
        float wx1 = px - x0f, wx0 = 1.f - wx1;
        int iy0 = (int)y0f, ix0 = (int)x0f;
        int iy1 = iy0 + 1,  ix1 = ix0 + 1;
        bool vy0 = (iy0 >= 0) && (iy0 < HH), vy1 = (iy1 >= 0) && (iy1 < HH);
        bool vx0 = (ix0 >= 0) && (ix0 < WW), vx1 = (ix1 >= 0) && (ix1 < WW);
        int cy0 = min(max(iy0, 0), HH-1), cy1 = min(max(iy1, 0), HH-1);
        int cx0 = min(max(ix0, 0), WW-1), cx1 = min(max(ix1, 0), WW-1);
        s_idx[l] = make_int4(cy0*WW + cx0, cy0*WW + cx1, cy1*WW + cx0, cy1*WW + cx1);
        s_wt[l]  = make_float4((vy0 && vx0) ? wy0*wx0 : 0.f,
                               (vy0 && vx1) ? wy0*wx1 : 0.f,
                               (vy1 && vx0) ? wy1*wx0 : 0.f,
                               (vy1 && vx1) ? wy1*wx1 : 0.f);
    }
    __syncthreads();

    const float* xb = x + (size_t)b * CIN * HWSZ;
    const uint4* wfrag4 = (const uint4*)g_wfrag;

    float acc[4][4][4];
    #pragma unroll
    for (int i = 0; i < 4; i++)
        #pragma unroll
        for (int j = 0; j < 4; j++)
            #pragma unroll
            for (int e = 0; e < 4; e++) acc[i][j][e] = 0.f;

    // ---- prologue: full serial gather of chunk 0 into buffer 0 ----
    {
        uint32_t* sBhi = (uint32_t*)(smem_raw);
        uint32_t* sBlo = sBhi + BHALF_U32;
        #pragma unroll
        for (int it = 0; it < 8; it++) {
            int l  = it*256 + tid;
            int kp = l >> 6, pl = l & 63;
            int ck = kp*2;
            int c  = ck / 9, k2 = ck - c*9;
            int4   id = s_idx[k2*PX + pl];
            float4 w  = s_wt [k2*PX + pl];
            const float* xp = xb + (size_t)c * HWSZ;
            float v0 = w.x*__ldg(xp+id.x) + w.y*__ldg(xp+id.y)
                     + w.z*__ldg(xp+id.z) + w.w*__ldg(xp+id.w);
            int ck1 = ck + 1;
            int c1  = ck1 / 9, k21 = ck1 - c1*9;
            id = s_idx[k21*PX + pl];
            w  = s_wt [k21*PX + pl];
            xp = xb + (size_t)c1 * HWSZ;
            float v1 = w.x*__ldg(xp+id.x) + w.y*__ldg(xp+id.y)
                     + w.z*__ldg(xp+id.z) + w.w*__ldg(xp+id.w);

            __nv_bfloat16 h0 = __float2bfloat16(v0);
            __nv_bfloat16 h1 = __float2bfloat16(v1);
            __nv_bfloat16 l0 = __float2bfloat16(v0 - __bfloat162float(h0));
            __nv_bfloat16 l1 = __float2bfloat16(v1 - __bfloat162float(h1));
            sBhi[kp*BSTRIDE + pl] = (uint32_t)__bfloat16_as_ushort(h0)
                                  | ((uint32_t)__bfloat16_as_ushort(h1) << 16);
            sBlo[kp*BSTRIDE + pl] = (uint32_t)__bfloat16_as_ushort(l0)
                                  | ((uint32_t)__bfloat16_as_ushort(l1) << 16);
        }
    }
    __syncthreads();

    #pragma unroll 1
    for (int chunk = 0; chunk < NCHUNK; ++chunk) {
        uint32_t* sBhi = (uint32_t*)(smem_raw + (chunk & 1) * BBUF_BYTES);
        uint32_t* sBlo = sBhi + BHALF_U32;
        uint32_t* nBhi = (uint32_t*)(smem_raw + ((chunk + 1) & 1) * BBUF_BYTES);
        uint32_t* nBlo = nBhi + BHALF_U32;
        bool pf = (chunk + 1 < NCHUNK);
        int nck0 = (chunk + 1) * KC;

        #pragma unroll
        for (int ks = 0; ks < 4; ks++) {
            // ---- (1) issue chunk+1 batch-ks gather LDGs (raw, no math) ----
            float pv[16];
            #pragma unroll
            for (int j = 0; j < 2; j++) {
                if (!pf) break;
                int it = ks*2 + j;
                int l  = it*256 + tid;
                int kp = l >> 6, pl = l & 63;
                int ck = nck0 + kp*2;
                int c  = ck / 9, k2 = ck - c*9;
                int4 id = s_idx[k2*PX + pl];
                const float* xp = xb + (size_t)c * HWSZ;
                pv[j*8+0] = __ldg(xp+id.x); pv[j*8+1] = __ldg(xp+id.y);
                pv[j*8+2] = __ldg(xp+id.z); pv[j*8+3] = __ldg(xp+id.w);
                int ck1 = ck + 1;
                int c1  = ck1 / 9, k21 = ck1 - c1*9;
                id = s_idx[k21*PX + pl];
                xp = xb + (size_t)c1 * HWSZ;
                pv[j*8+4] = __ldg(xp+id.x); pv[j*8+5] = __ldg(xp+id.y);
                pv[j*8+6] = __ldg(xp+id.z); pv[j*8+7] = __ldg(xp+id.w);
            }

            // ---- (2) MMA ks-step for current chunk (hides LDG latency) ----
            uint32_t bh0[4], bh1[4], bl0[4], bl1[4];
            #pragma unroll
            for (int nb = 0; nb < 4; nb++) {
                int col = ncol*32 + nb*8 + (lane >> 2);
                int kpb = ks*8 + (lane & 3);
                bh0[nb] = sBhi[ kpb     *BSTRIDE + col];
                bh1[nb] = sBhi[(kpb + 4)*BSTRIDE + col];
                bl0[nb] = sBlo[ kpb     *BSTRIDE + col];
                bl1[nb] = sBlo[(kpb + 4)*BSTRIDE + col];
            }
            #pragma unroll
            for (int mb = 0; mb < 4; mb++) {
                int mbg = mrow*4 + mb;
                uint4 ahi = __ldg(wfrag4 + ((size_t)((chunk*2    )*16 + mbg)*4 + ks)*32 + lane);
                uint4 alo = __ldg(wfrag4 + ((size_t)((chunk*2 + 1)*16 + mbg)*4 + ks)*32 + lane);
                #pragma unroll
                for (int nb = 0; nb < 4; nb++) {
                    mma16816(acc[mb][nb], ahi, bh0[nb], bh1[nb]);
                    mma16816(acc[mb][nb], ahi, bl0[nb], bl1[nb]);
                    mma16816(acc[mb][nb], alo, bh0[nb], bh1[nb]);
                }
            }

            // ---- (3) combine + split + store prefetched batch ----
            #pragma unroll
            for (int j = 0; j < 2; j++) {
                if (!pf) break;
                int it = ks*2 + j;
                int l  = it*256 + tid;
                int kp = l >> 6, pl = l & 63;
                int ck = nck0 + kp*2;
                int c  = ck / 9, k2 = ck - c*9;
                float4 w = s_wt[k2*PX + pl];
                float v0 = w.x*pv[j*8+0] + w.y*pv[j*8+1]
                         + w.z*pv[j*8+2] + w.w*pv[j*8+3];
                int ck1 = ck + 1;
                int c1  = ck1 / 9, k21 = ck1 - c1*9;
                w = s_wt[k21*PX + pl];
                float v1 = w.x*pv[j*8+4] + w.y*pv[j*8+5]
                         + w.z*pv[j*8+6] + w.w*pv[j*8+7];

                __nv_bfloat16 h0 = __float2bfloat16(v0);
                __nv_bfloat16 h1 = __float2bfloat16(v1);
                __nv_bfloat16 l0 = __float2bfloat16(v0 - __bfloat162float(h0));
                __nv_bfloat16 l1 = __float2bfloat16(v1 - __bfloat162float(h1));
                nBhi[kp*BSTRIDE + pl] = (uint32_t)__bfloat16_as_ushort(h0)
                                      | ((uint32_t)__bfloat16_as_ushort(h1) << 16);
                nBlo[kp*BSTRIDE + pl] = (uint32_t)__bfloat16_as_ushort(l0)
                                      | ((uint32_t)__bfloat16_as_ushort(l1) << 16);
            }
        }
        __syncthreads();   // buffer swap: chunk done, chunk+1 fully stored
    }

    // ---- epilogue: bias + store (float2 per fragment pair) ----
    #pragma unroll
    for (int mb = 0; mb < 4; mb++) {
        int o0 = mrow*64 + mb*16 + (lane >> 2);
        float bd0 = b_def[o0], bd8 = b_def[o0 + 8];
        float* r0 = out + ((size_t)b*COUT + o0)*HWSZ + pbase + ncol*32 + (lane & 3)*2;
        float* r8 = r0 + (size_t)8*HWSZ;
        #pragma unroll
        for (int nb = 0; nb < 4; nb++) {
            float2 v0 = make_float2(acc[mb][nb][0] + bd0, acc[mb][nb][1] + bd0);
            float2 v8 = make_float2(acc[mb][nb][2] + bd8, acc[mb][nb][3] + bd8);
            *(float2*)(r0 + nb*8) = v0;
            *(float2*)(r8 + nb*8) = v8;
        }
    }
}

// ---------------------------------------------------------------------------
extern "C" void kernel_launch(void* const* d_in, const int* in_sizes, int n_in,
                              void* d_out, int out_size)
{
    const float* x     = (const float*)d_in[0];
    const float* w_off = (const float*)d_in[1];
    const float* b_off = (const float*)d_in[2];
    const float* w_def = (const float*)d_in[3];
    const float* b_def = (const float*)d_in[4];
    float* out = (float*)d_out;

    cudaFuncSetAttribute(dcn_hmma, cudaFuncAttributeMaxDynamicSharedMemorySize, SMEM_BYTES);

    offset_part<<<dim3(HWSZ/256, NB, ZSPLIT), 128>>>(x, w_off);
    offset_reduce<<<(NB*NOFF*HWSZ + 255)/256, 256>>>(b_off);
    wprep<<<(NCHUNK*2*16*32*16 + 255)/256, 256>>>(w_def);
    dcn_hmma<<<NB*HWSZ/PX, 256, SMEM_BYTES>>>(x, out, b_def);
}

// round 8
// speedup vs baseline: 1.4937x; 1.4666x over previous
#include <cuda_runtime.h>
#include <cuda_fp16.h>
#include <stdint.h>

#define NB   4
#define CIN  256
#define COUT 256
#define HH   96
#define WW   96
#define HWSZ (HH*WW)          // 9216
#define KK2  9
#define CK   (CIN*KK2)        // 2304
#define NOFF 18
#define NCHUNK 36             // CK / 64
#define KC   64
#define ZSPLIT 8
#define PX   64               // pixels per CTA

// ---- dynamic smem layout for dcn_hmma (u32 / bytes) ----
// B buffer: 32 kpairs x 72 u32 (stride-72 = conflict-free), fp16x2.
#define BSTRIDE   72
#define BBUF_U32  (32*BSTRIDE)          // 2304 u32 = 9216 B
#define BBUF_BYTES (BBUF_U32*4)         // 9216 B
#define OFF_IDX    (2*BBUF_BYTES)       // 18432
#define OFF_SWT    (OFF_IDX + KK2*PX*16)// 27648
#define SMEM_BYTES (OFF_SWT + KK2*PX*16)// 36864

// ---- device scratch (allocation-free rule) ----
__device__ float    g_off_part[ZSPLIT*NB*NOFF*HWSZ];   // 21 MB
__device__ float    g_offset[NB*NOFF*HWSZ];            // 2.65 MB
__device__ uint32_t g_wfrag[NCHUNK*16*32*16];          // 1.18 MB: fp16 A fragments

// ---------------------------------------------------------------------------
// Kernel A1: partial offset conv (32 Cin channels per block.z chunk)
// ---------------------------------------------------------------------------
__global__ __launch_bounds__(128) void offset_part(
    const float* __restrict__ x, const float* __restrict__ w_off)
{
    __shared__ float ws[8*NOFF*KK2];
    int b   = blockIdx.y, z = blockIdx.z;
    int tid = threadIdx.x;
    int p0  = blockIdx.x * 256 + tid;
    int p1  = p0 + 128;
    int yy0 = p0 / WW, xx0 = p0 % WW;
    int yy1 = p1 / WW, xx1 = p1 % WW;

    float acc[2][NOFF];
    #pragma unroll
    for (int j = 0; j < NOFF; j++) { acc[0][j] = 0.f; acc[1][j] = 0.f; }

    const float* xb = x + (size_t)b * CIN * HWSZ;
    const int CPZ = CIN / ZSPLIT;   // 32

    for (int c0 = z*CPZ; c0 < z*CPZ + CPZ; c0 += 8) {
        __syncthreads();
        for (int l = tid; l < 8*NOFF*KK2; l += 128) {
            int ci = l / (NOFF*KK2);
            int r  = l % (NOFF*KK2);
            int j  = r / KK2, k = r % KK2;
            ws[l] = w_off[((size_t)(j*CIN + c0 + ci))*KK2 + k];
        }
        __syncthreads();
        #pragma unroll 2
        for (int ci = 0; ci < 8; ci++) {
            const float* xp = xb + (size_t)(c0 + ci) * HWSZ;
            float xv0[9], xv1[9];
            #pragma unroll
            for (int ky = 0; ky < 3; ky++) {
                #pragma unroll
                for (int kx = 0; kx < 3; kx++) {
                    int iy = yy0 - 1 + ky, ix = xx0 - 1 + kx;
                    xv0[ky*3+kx] = (iy >= 0 && iy < HH && ix >= 0 && ix < WW) ? xp[iy*WW + ix] : 0.f;
                    iy = yy1 - 1 + ky; ix = xx1 - 1 + kx;
                    xv1[ky*3+kx] = (iy >= 0 && iy < HH && ix >= 0 && ix < WW) ? xp[iy*WW + ix] : 0.f;
                }
            }
            const float* wsc = ws + ci * NOFF * KK2;
            #pragma unroll
            for (int j = 0; j < NOFF; j++) {
                #pragma unroll
                for (int k = 0; k < KK2; k++) {
                    float wv = wsc[j*KK2 + k];
                    acc[0][j] += xv0[k] * wv;
                    acc[1][j] += xv1[k] * wv;
                }
            }
        }
    }
    size_t zb = (size_t)z * NB * NOFF * HWSZ;
    #pragma unroll
    for (int j = 0; j < NOFF; j++) {
        g_off_part[zb + ((size_t)b*NOFF + j)*HWSZ + p0] = acc[0][j];
        g_off_part[zb + ((size_t)b*NOFF + j)*HWSZ + p1] = acc[1][j];
    }
}

// Kernel A2: sum partials + bias
__global__ void offset_reduce(const float* __restrict__ b_off)
{
    int i = blockIdx.x * 256 + threadIdx.x;
    if (i < NB*NOFF*HWSZ) {
        int j = (i / HWSZ) % NOFF;
        float s = b_off[j];
        #pragma unroll
        for (int z = 0; z < ZSPLIT; z++) s += g_off_part[(size_t)z*NB*NOFF*HWSZ + i];
        g_offset[i] = s;
    }
}

// ---------------------------------------------------------------------------
// Kernel B: pack w_def into fp16 A-fragments (m16n8k16 layout).
// u32 index bits (lane fastest below i): [i:2][lane:5][ks:2][mb:4][chunk]
//   o = mb*16 + lane/4 + (i&1)*8
//   k = chunk*64 + ks*16 + (lane%4)*2 + (i>>1)*8   (pack k, k+1 as fp16x2)
// ---------------------------------------------------------------------------
__global__ void wprep(const float* __restrict__ w_def)
{
    int idx = blockIdx.x * 256 + threadIdx.x;
    if (idx >= NCHUNK*16*32*16) return;
    int i     =  idx        & 3;
    int lane  = (idx >> 2)  & 31;
    int ks    = (idx >> 7)  & 3;
    int mb    = (idx >> 9)  & 15;
    int chunk =  idx >> 13;

    int o = mb*16 + (lane >> 2) + (i & 1)*8;
    int k = chunk*64 + ks*16 + (lane & 3)*2 + (i >> 1)*8;
    float w0 = w_def[(size_t)o*CK + k];
    float w1 = w_def[(size_t)o*CK + k + 1];

    __half2 v = __floats2half2_rn(w0, w1);
    g_wfrag[idx] = *(uint32_t*)&v;
}

// ---------------------------------------------------------------------------
__device__ __forceinline__ void mma16816(float* c, uint4 a, uint32_t b0, uint32_t b1)
{
    asm volatile(
        "mma.sync.aligned.m16n8k16.row.col.f32.f16.f16.f32 "
        "{%0,%1,%2,%3}, {%4,%5,%6,%7}, {%8,%9}, {%0,%1,%2,%3};"
        : "+f"(c[0]), "+f"(c[1]), "+f"(c[2]), "+f"(c[3])
        : "r"(a.x), "r"(a.y), "r"(a.z), "r"(a.w), "r"(b0), "r"(b1));
}

// ---------------------------------------------------------------------------
// Kernel C: fused bilinear-gather + single-pass fp16 HMMA GEMM, pipelined.
// CTA: 64 px x 256 Cout; 256 threads = 8 warps (4 m-rows x 2 n-cols),
// warp tile 64 x 32. grid = NB*HWSZ/64 = 576. 2 CTAs/SM.
// ---------------------------------------------------------------------------
__global__ void __launch_bounds__(256, 2) dcn_hmma(
    const float* __restrict__ x,
    float* __restrict__ out,
    const float* __restrict__ b_def)
{
    extern __shared__ __align__(16) unsigned char smem_raw[];
    int4*   s_idx = (int4*)  (smem_raw + OFF_IDX);
    float4* s_wt  = (float4*)(smem_raw + OFF_SWT);

    int tid = threadIdx.x, wid = tid >> 5, lane = tid & 31;
    int mrow = wid >> 1, ncol = wid & 1;

    int gp    = blockIdx.x * PX;
    int b     = gp / HWSZ;
    int pbase = gp % HWSZ;

    // Phase 1: bilinear corner indices & weights for this 64-pixel tile
    for (int l = tid; l < KK2*PX; l += 256) {
        int k2 = l >> 6, pl = l & 63;
        int p  = pbase + pl;
        int oy = p / WW, ox = p % WW;
        float offy = g_offset[((size_t)b*NOFF + k2*2    )*HWSZ + p];
        float offx = g_offset[((size_t)b*NOFF + k2*2 + 1)*HWSZ + p];
        int ky = k2 / 3, kx = k2 % 3;
        float py = (float)(oy - 1 + ky) + offy;
        float px = (float)(ox - 1 + kx) + offx;
        float y0f = floorf(py), x0f = floorf(px);
        float wy1 = py - y0f, wy0 = 1.f - wy1;
        float wx1 = px - x0f, wx0 = 1.f - wx1;
        int iy0 = (int)y0f, ix0 = (int)x0f;
        int iy1 = iy0 + 1,  ix1 = ix0 + 1;
        bool vy0 = (iy0 >= 0) && (iy0 < HH), vy1 = (iy1 >= 0) && (iy1 < HH);
        bool vx0 = (ix0 >= 0) && (ix0 < WW), vx1 = (ix1 >= 0) && (ix1 < WW);
        int cy0 = min(max(iy0, 0), HH-1), cy1 = min(max(iy1, 0), HH-1);
        int cx0 = min(max(ix0, 0), WW-1), cx1 = min(max(ix1, 0), WW-1);
        s_idx[l] = make_int4(cy0*WW + cx0, cy0*WW + cx1, cy1*WW + cx0, cy1*WW + cx1);
        s_wt[l]  = make_float4((vy0 && vx0) ? wy0*wx0 : 0.f,
                               (vy0 && vx1) ? wy0*wx1 : 0.f,
                               (vy1 && vx0) ? wy1*wx0 : 0.f,
                               (vy1 && vx1) ? wy1*wx1 : 0.f);
    }
    __syncthreads();

    const float* xb = x + (size_t)b * CIN * HWSZ;
    const uint4* wfrag4 = (const uint4*)g_wfrag;

    float acc[4][4][4];
    #pragma unroll
    for (int i = 0; i < 4; i++)
        #pragma unroll
        for (int j = 0; j < 4; j++)
            #pragma unroll
            for (int e = 0; e < 4; e++) acc[i][j][e] = 0.f;

    // ---- gather + fp16 pack for a chunk into buffer bb ----
    auto gather_store = [&](int chunk, int bb) {
        uint32_t* sB = (uint32_t*)(smem_raw + bb * BBUF_BYTES);
        int ck0 = chunk * KC;
        #pragma unroll
        for (int it = 0; it < 8; it++) {
            int l  = it*256 + tid;
            int kp = l >> 6, pl = l & 63;
            int ck = ck0 + kp*2;
            int c  = ck / 9, k2 = ck - c*9;
            int4   id = s_idx[k2*PX + pl];
            float4 w  = s_wt [k2*PX + pl];
            const float* xp = xb + (size_t)c * HWSZ;
            float v0 = w.x*__ldg(xp+id.x) + w.y*__ldg(xp+id.y)
                     + w.z*__ldg(xp+id.z) + w.w*__ldg(xp+id.w);
            int ck1 = ck + 1;
            int c1  = ck1 / 9, k21 = ck1 - c1*9;
            id = s_idx[k21*PX + pl];
            w  = s_wt [k21*PX + pl];
            xp = xb + (size_t)c1 * HWSZ;
            float v1 = w.x*__ldg(xp+id.x) + w.y*__ldg(xp+id.y)
                     + w.z*__ldg(xp+id.z) + w.w*__ldg(xp+id.w);

            __half2 hv = __floats2half2_rn(v0, v1);
            sB[kp*BSTRIDE + pl] = *(uint32_t*)&hv;
        }
    };

    // prologue: fill buffer 0 with chunk 0
    gather_store(0, 0);
    __syncthreads();

    #pragma unroll 1
    for (int chunk = 0; chunk < NCHUNK; ++chunk) {
        // produce chunk+1 into the other buffer BEFORE consuming chunk
        if (chunk + 1 < NCHUNK) gather_store(chunk + 1, (chunk + 1) & 1);

        uint32_t* sB = (uint32_t*)(smem_raw + (chunk & 1) * BBUF_BYTES);

        // ---- HMMA: single fp16 pass ----
        #pragma unroll
        for (int ks = 0; ks < 4; ks++) {
            uint32_t bh0[4], bh1[4];
            #pragma unroll
            for (int nb = 0; nb < 4; nb++) {
                int col = ncol*32 + nb*8 + (lane >> 2);
                int kpb = ks*8 + (lane & 3);
                bh0[nb] = sB[ kpb     *BSTRIDE + col];
                bh1[nb] = sB[(kpb + 4)*BSTRIDE + col];
            }
            #pragma unroll
            for (int mb = 0; mb < 4; mb++) {
                int mbg = mrow*4 + mb;
                uint4 a = __ldg(wfrag4 + ((size_t)(chunk*16 + mbg)*4 + ks)*32 + lane);
                #pragma unroll
                for (int nb = 0; nb < 4; nb++)
                    mma16816(acc[mb][nb], a, bh0[nb], bh1[nb]);
            }
        }
        __syncthreads();
    }

    // ---- epilogue: bias + store (float2 per fragment pair) ----
    #pragma unroll
    for (int mb = 0; mb < 4; mb++) {
        int o0 = mrow*64 + mb*16 + (lane >> 2);
        float bd0 = b_def[o0], bd8 = b_def[o0 + 8];
        float* r0 = out + ((size_t)b*COUT + o0)*HWSZ + pbase + ncol*32 + (lane & 3)*2;
        float* r8 = r0 + (size_t)8*HWSZ;
        #pragma unroll
        for (int nb = 0; nb < 4; nb++) {
            float2 v0 = make_float2(acc[mb][nb][0] + bd0, acc[mb][nb][1] + bd0);
            float2 v8 = make_float2(acc[mb][nb][2] + bd8, acc[mb][nb][3] + bd8);
            *(float2*)(r0 + nb*8) = v0;
            *(float2*)(r8 + nb*8) = v8;
        }
    }
}

// ---------------------------------------------------------------------------
extern "C" void kernel_launch(void* const* d_in, const int* in_sizes, int n_in,
                              void* d_out, int out_size)
{
    const float* x     = (const float*)d_in[0];
    const float* w_off = (const float*)d_in[1];
    const float* b_off = (const float*)d_in[2];
    const float* w_def = (const float*)d_in[3];
    const float* b_def = (const float*)d_in[4];
    float* out = (float*)d_out;

    cudaFuncSetAttribute(dcn_hmma, cudaFuncAttributeMaxDynamicSharedMemorySize, SMEM_BYTES);

    offset_part<<<dim3(HWSZ/256, NB, ZSPLIT), 128>>>(x, w_off);
    offset_reduce<<<(NB*NOFF*HWSZ + 255)/256, 256>>>(b_off);
    wprep<<<(NCHUNK*16*32*16 + 255)/256, 256>>>(w_def);
    dcn_hmma<<<NB*HWSZ/PX, 256, SMEM_BYTES>>>(x, out, b_def);
}